// round 7
// baseline (speedup 1.0000x reference)
#include <cuda_runtime.h>
#include <cuda_bf16.h>
#include <cstdint>

#define BATCH 8192
#define IN_OUT_DIM 1024
#define HALF 512
#define MID 4096

// Weight element offsets in the packed transposed-weight buffers.
#define WO0 0                       // Wt0 [4096,512]
#define WO1 (WO0 + 4096*512)        // Wt1 [4096,4096]
#define WO2 (WO1 + 4096*4096)
#define WO3 (WO2 + 4096*4096)
#define WO4 (WO3 + 4096*4096)
#define WO5 (WO4 + 4096*4096)       // Wt5 [512,4096]
#define WTOT (WO5 + 512*4096)

// ---------------------------------------------------------------------------
// Scratch (allocation-free rule -> device globals)
// ---------------------------------------------------------------------------
__device__ __align__(1024) unsigned short g_odd_hi[BATCH * HALF];
__device__ __align__(1024) unsigned short g_odd_lo[BATCH * HALF];
__device__ __align__(1024) unsigned short g_a_hi[2][BATCH * MID];
__device__ __align__(1024) unsigned short g_a_lo[2][BATCH * MID];
__device__ __align__(1024) unsigned short g_w_hi[WTOT];
__device__ __align__(1024) unsigned short g_w_lo[WTOT];
__device__ __align__(1024) float g_m[BATCH * HALF];

// ---------------------------------------------------------------------------
// PTX helpers (sm_80-level: cp.async, ldmatrix, mma.sync)
// ---------------------------------------------------------------------------
__device__ __forceinline__ uint32_t smem_to_u32(const void* p) {
    uint32_t a;
    asm("{ .reg .u64 t; cvta.to.shared.u64 t, %1; cvt.u32.u64 %0, t; }" : "=r"(a) : "l"(p));
    return a;
}

__device__ __forceinline__ void cp_async16(uint32_t dst, const void* src) {
    asm volatile("cp.async.cg.shared.global [%0], [%1], 16;" :: "r"(dst), "l"(src));
}
__device__ __forceinline__ void cp_commit() {
    asm volatile("cp.async.commit_group;" ::: "memory");
}
template <int N>
__device__ __forceinline__ void cp_wait() {
    asm volatile("cp.async.wait_group %0;" :: "n"(N) : "memory");
}

#define LDMATRIX_X4(r0, r1, r2, r3, addr) \
    asm volatile("ldmatrix.sync.aligned.m8n8.x4.shared.b16 {%0,%1,%2,%3}, [%4];" \
                 : "=r"(r0), "=r"(r1), "=r"(r2), "=r"(r3) : "r"(addr))

// D(f32) += A(bf16,row) * B(bf16,col);  C/D 4 regs, A 4 regs, B 2 regs
__device__ __forceinline__ void mma_bf16(float* c, const uint32_t* a, const uint32_t* b) {
    asm volatile(
        "mma.sync.aligned.m16n8k16.row.col.f32.bf16.bf16.f32 "
        "{%0,%1,%2,%3}, {%4,%5,%6,%7}, {%8,%9}, {%0,%1,%2,%3};"
        : "+f"(c[0]), "+f"(c[1]), "+f"(c[2]), "+f"(c[3])
        : "r"(a[0]), "r"(a[1]), "r"(a[2]), "r"(a[3]), "r"(b[0]), "r"(b[1]));
}

// ---------------------------------------------------------------------------
// fp32 -> (bf16 hi, bf16 lo) split
// ---------------------------------------------------------------------------
__device__ __forceinline__ void split_bf16(float v, unsigned short& h, unsigned short& l) {
    __nv_bfloat16 hb = __float2bfloat16_rn(v);
    float r = v - __bfloat162float(hb);
    __nv_bfloat16 lb = __float2bfloat16_rn(r);
    h = __bfloat16_as_ushort(hb);
    l = __bfloat16_as_ushort(lb);
}

// ---------------------------------------------------------------------------
// Prep kernels
// ---------------------------------------------------------------------------
__global__ void extract_odd_split(const float* __restrict__ x,
                                  unsigned short* __restrict__ oh,
                                  unsigned short* __restrict__ ol) {
    int i = blockIdx.x * blockDim.x + threadIdx.x;
    if (i < BATCH * HALF) {
        float2 v = reinterpret_cast<const float2*>(x)[i];
        split_bf16(v.y, oh[i], ol[i]);
    }
}

// W [K,N] fp32 (row-major) -> Wt hi/lo [N,K] bf16
__global__ void transpose_split(const float* __restrict__ W,
                                unsigned short* __restrict__ Th,
                                unsigned short* __restrict__ Tl,
                                int K, int N) {
    __shared__ float t[32][33];
    int n0 = blockIdx.x * 32, k0 = blockIdx.y * 32;
    int tx = threadIdx.x, ty = threadIdx.y;
    #pragma unroll
    for (int i = ty; i < 32; i += 8)
        t[i][tx] = W[(size_t)(k0 + i) * N + n0 + tx];
    __syncthreads();
    #pragma unroll
    for (int i = ty; i < 32; i += 8) {
        float v = t[tx][i];
        unsigned short h, l;
        split_bf16(v, h, l);
        size_t idx = (size_t)(n0 + i) * K + k0 + tx;
        Th[idx] = h;
        Tl[idx] = l;
    }
}

// ---------------------------------------------------------------------------
// Split-bf16 HMMA GEMM: C[M,N] = A[M,K] @ Bt[N,K]^T + bias
// BM=128, BN=256, BK=32; 512 threads (16 warps, 2x8 of 64x32 warp tiles);
// 4-stage cp.async pipeline, ONE __syncthreads per mainloop iteration;
// 64B-row swizzled smem; mma.sync m16n8k16 bf16.
// D accumulates Ahi*Bhi + Ahi*Blo + Alo*Bhi in fp32 registers.
// ---------------------------------------------------------------------------
#define BM 128
#define BN 256
#define BK 32
#define NTHREADS 512
#define NSTAGE 4
#define AH_OFF 0
#define AL_OFF 8192
#define BH_OFF 16384
#define BL_OFF 32768
#define STAGE_SZ 49152
#define SMEM_TOTAL (NSTAGE * STAGE_SZ + 1024)

// 64B rows (32 bf16). 8-row ldmatrix accesses stay conflict-free:
// sw = (row*64 + col) ^ ((row&3)<<4)
__device__ __forceinline__ uint32_t swz64(int row, int bytecol) {
    return (uint32_t)(row * 64 + bytecol) ^ (uint32_t)((row & 3) << 4);
}

__device__ __forceinline__ void load_stage(
    uint32_t stage_base,
    const unsigned short* Ah, const unsigned short* Al,
    const unsigned short* Bh, const unsigned short* Bl,
    int lda, int tid) {
    // A: 128 rows x 64B = 512 chunks of 16B -> 1 per thread (per operand)
    {
        int row = tid >> 2;
        int col = (tid & 3) * 16;
        uint32_t sw = swz64(row, col);
        cp_async16(stage_base + AH_OFF + sw, (const char*)(Ah + (size_t)row * lda) + col);
        cp_async16(stage_base + AL_OFF + sw, (const char*)(Al + (size_t)row * lda) + col);
    }
    // B: 256 rows x 64B = 1024 chunks -> 2 per thread (per operand)
    #pragma unroll
    for (int j = 0; j < 2; j++) {
        int c = tid + NTHREADS * j;
        int row = c >> 2;
        int col = (c & 3) * 16;
        uint32_t sw = swz64(row, col);
        cp_async16(stage_base + BH_OFF + sw, (const char*)(Bh + (size_t)row * lda) + col);
        cp_async16(stage_base + BL_OFF + sw, (const char*)(Bl + (size_t)row * lda) + col);
    }
}

template <bool RELU, bool FINAL>
__global__ void __launch_bounds__(NTHREADS, 1)
mma_gemm(const unsigned short* __restrict__ Ah, const unsigned short* __restrict__ Al,
         const unsigned short* __restrict__ Bh, const unsigned short* __restrict__ Bl,
         const float* __restrict__ bias,
         unsigned short* __restrict__ Ch, unsigned short* __restrict__ Cl,
         float* __restrict__ Cf,
         int N, int K) {
    extern __shared__ char dyn_smem[];
    const uint32_t sbase = (smem_to_u32(dyn_smem) + 1023u) & ~1023u;

    const int tid = threadIdx.x;
    const int wid = tid >> 5;
    const int lane = tid & 31;
    const int warp_m = wid & 1;   // 2 warps over M (64 rows each)
    const int warp_n = wid >> 1;  // 8 warps over N (32 cols each)

    const int m0 = blockIdx.y * BM;
    const int n0 = blockIdx.x * BN;
    const unsigned short* Ath = Ah + (size_t)m0 * K;
    const unsigned short* Atl = Al + (size_t)m0 * K;
    const unsigned short* Bth = Bh + (size_t)n0 * K;
    const unsigned short* Btl = Bl + (size_t)n0 * K;

    const int niter = K / BK;

    // Prologue: fill NSTAGE-1 stages
    #pragma unroll
    for (int s = 0; s < NSTAGE - 1; s++) {
        load_stage(sbase + s * STAGE_SZ,
                   Ath + s * BK, Atl + s * BK, Bth + s * BK, Btl + s * BK, K, tid);
        cp_commit();
    }

    float acc[4][4][4];
    #pragma unroll
    for (int mi = 0; mi < 4; mi++)
        #pragma unroll
        for (int nj = 0; nj < 4; nj++)
            #pragma unroll
            for (int q = 0; q < 4; q++) acc[mi][nj][q] = 0.0f;

    // Per-thread ldmatrix address components
    const int a_row_base = warp_m * 64 + (lane & 15);                // + mi*16
    const int a_col_sel = ((lane >> 4) & 1) * 16;                    // + kk*32
    const int b_row_base = warp_n * 32 + (lane & 7) + ((lane >> 4) & 1) * 8;  // + njp*16
    const int b_col_sel = ((lane >> 3) & 1) * 16;                    // + kk*32

    for (int i = 0; i < niter; i++) {
        cp_wait<NSTAGE - 2>();   // stage i resident
        __syncthreads();         // all warps past compute(i-1); slot (i-1)%4 free

        // Issue next-stage loads first so they overlap compute(i)
        if (i + NSTAGE - 1 < niter) {
            int kb = (i + NSTAGE - 1) * BK;
            load_stage(sbase + ((i + NSTAGE - 1) % NSTAGE) * STAGE_SZ,
                       Ath + kb, Atl + kb, Bth + kb, Btl + kb, K, tid);
        }
        cp_commit();  // uniform group accounting (possibly empty)

        const uint32_t so = sbase + (i % NSTAGE) * STAGE_SZ;

        #pragma unroll
        for (int kk = 0; kk < 2; kk++) {
            uint32_t a_hi[4][4], a_lo[4][4];
            const int acol = a_col_sel + kk * 32;
            const int bcol = b_col_sel + kk * 32;
            #pragma unroll
            for (int mi = 0; mi < 4; mi++) {
                const int row = a_row_base + mi * 16;
                const uint32_t sw = swz64(row, acol);
                LDMATRIX_X4(a_hi[mi][0], a_hi[mi][1], a_hi[mi][2], a_hi[mi][3],
                            so + AH_OFF + sw);
                LDMATRIX_X4(a_lo[mi][0], a_lo[mi][1], a_lo[mi][2], a_lo[mi][3],
                            so + AL_OFF + sw);
            }
            #pragma unroll
            for (int njp = 0; njp < 2; njp++) {
                uint32_t b_hi[2][2], b_lo[2][2];
                const int row = b_row_base + njp * 16;
                const uint32_t sw = swz64(row, bcol);
                LDMATRIX_X4(b_hi[0][0], b_hi[0][1], b_hi[1][0], b_hi[1][1],
                            so + BH_OFF + sw);
                LDMATRIX_X4(b_lo[0][0], b_lo[0][1], b_lo[1][0], b_lo[1][1],
                            so + BL_OFF + sw);
                #pragma unroll
                for (int mi = 0; mi < 4; mi++) {
                    #pragma unroll
                    for (int njq = 0; njq < 2; njq++) {
                        const int nj = 2 * njp + njq;
                        mma_bf16(acc[mi][nj], a_hi[mi], b_hi[njq]);
                        mma_bf16(acc[mi][nj], a_hi[mi], b_lo[njq]);
                        mma_bf16(acc[mi][nj], a_lo[mi], b_hi[njq]);
                    }
                }
            }
        }
    }

    // Epilogue: c0,c1 -> row g, cols p,p+1; c2,c3 -> row g+8
    const int g = lane >> 2;
    const int p = (lane & 3) * 2;
    #pragma unroll
    for (int mi = 0; mi < 4; mi++) {
        #pragma unroll
        for (int nj = 0; nj < 4; nj++) {
            const int col = n0 + warp_n * 32 + nj * 8 + p;
            const float bx = bias[col];
            const float by = bias[col + 1];
            #pragma unroll
            for (int half = 0; half < 2; half++) {
                const int r = m0 + warp_m * 64 + mi * 16 + g + half * 8;
                float v0 = acc[mi][nj][2 * half + 0] + bx;
                float v1 = acc[mi][nj][2 * half + 1] + by;
                if (RELU) {
                    v0 = fmaxf(v0, 0.0f);
                    v1 = fmaxf(v1, 0.0f);
                }
                if (FINAL) {
                    float2 o = make_float2(v0, v1);
                    *reinterpret_cast<float2*>(Cf + (size_t)r * N + col) = o;
                } else {
                    unsigned short h0, l0, h1, l1;
                    split_bf16(v0, h0, l0);
                    split_bf16(v1, h1, l1);
                    *reinterpret_cast<uint32_t*>(Ch + (size_t)r * N + col) =
                        ((uint32_t)h1 << 16) | h0;
                    *reinterpret_cast<uint32_t*>(Cl + (size_t)r * N + col) =
                        ((uint32_t)l1 << 16) | l0;
                }
            }
        }
    }
}

// ---------------------------------------------------------------------------
// Finalize: out[b,2k] = x[b,2k] + m[b,k]; out[b,2k+1] = x[b,2k+1]; ldj tail.
// ---------------------------------------------------------------------------
__global__ void finalize_kernel(const float* __restrict__ x,
                                const float* __restrict__ m,
                                const float* __restrict__ ldj,
                                float* __restrict__ out,
                                int tail) {
    int i = blockIdx.x * blockDim.x + threadIdx.x;
    if (i < BATCH * HALF) {
        float2 v = reinterpret_cast<const float2*>(x)[i];
        float2 o;
        o.x = v.x + m[i];
        o.y = v.y;
        reinterpret_cast<float2*>(out)[i] = o;
    }
    if (i < tail) {
        out[BATCH * IN_OUT_DIM + i] = ldj[i];
    }
}

// ---------------------------------------------------------------------------
extern "C" void kernel_launch(void* const* d_in, const int* in_sizes, int n_in,
                              void* d_out, int out_size) {
    const float* x   = (const float*)d_in[0];
    const float* ldj = (const float*)d_in[1];
    const float* W[6] = {(const float*)d_in[2], (const float*)d_in[4],
                         (const float*)d_in[6], (const float*)d_in[8],
                         (const float*)d_in[10], (const float*)d_in[12]};
    const float* b[6] = {(const float*)d_in[3], (const float*)d_in[5],
                         (const float*)d_in[7], (const float*)d_in[9],
                         (const float*)d_in[11], (const float*)d_in[13]};
    float* out = (float*)d_out;

    unsigned short *odd_hi, *odd_lo, *a_hi, *a_lo, *w_hi, *w_lo;
    float* m;
    cudaGetSymbolAddress((void**)&odd_hi, g_odd_hi);
    cudaGetSymbolAddress((void**)&odd_lo, g_odd_lo);
    cudaGetSymbolAddress((void**)&a_hi, g_a_hi);
    cudaGetSymbolAddress((void**)&a_lo, g_a_lo);
    cudaGetSymbolAddress((void**)&w_hi, g_w_hi);
    cudaGetSymbolAddress((void**)&w_lo, g_w_lo);
    cudaGetSymbolAddress((void**)&m, g_m);

    unsigned short* ah[2] = {a_hi, a_hi + (size_t)BATCH * MID};
    unsigned short* al[2] = {a_lo, a_lo + (size_t)BATCH * MID};
    const size_t woff[6] = {WO0, WO1, WO2, WO3, WO4, WO5};

    // --- prep ---
    const int n_pairs = BATCH * HALF;
    extract_odd_split<<<(n_pairs + 255) / 256, 256>>>(x, odd_hi, odd_lo);

    dim3 tb(32, 8);
    // W0 [512,4096] -> Wt0 [4096,512]
    transpose_split<<<dim3(4096 / 32, 512 / 32), tb>>>(W[0], w_hi + woff[0], w_lo + woff[0], 512, 4096);
    for (int i = 1; i <= 4; i++)
        transpose_split<<<dim3(4096 / 32, 4096 / 32), tb>>>(W[i], w_hi + woff[i], w_lo + woff[i], 4096, 4096);
    // W5 [4096,512] -> Wt5 [512,4096]
    transpose_split<<<dim3(512 / 32, 4096 / 32), tb>>>(W[5], w_hi + woff[5], w_lo + woff[5], 4096, 512);

    // --- GEMM chain ---
    cudaFuncSetAttribute(mma_gemm<true, false>,
                         cudaFuncAttributeMaxDynamicSharedMemorySize, SMEM_TOTAL);
    cudaFuncSetAttribute(mma_gemm<false, true>,
                         cudaFuncAttributeMaxDynamicSharedMemorySize, SMEM_TOTAL);

    dim3 blk(NTHREADS);
    dim3 grid_mid(MID / BN, BATCH / BM);   // (16, 64)
    dim3 grid_last(HALF / BN, BATCH / BM); // (2, 64)

    // L0: [8192,512] @ Wt0^T -> [8192,4096], relu
    mma_gemm<true, false><<<grid_mid, blk, SMEM_TOTAL>>>(
        odd_hi, odd_lo, w_hi + woff[0], w_lo + woff[0], b[0],
        ah[0], al[0], nullptr, MID, HALF);
    // L1..L4: [8192,4096] @ Wt^T -> [8192,4096], relu (ping-pong)
    mma_gemm<true, false><<<grid_mid, blk, SMEM_TOTAL>>>(
        ah[0], al[0], w_hi + woff[1], w_lo + woff[1], b[1],
        ah[1], al[1], nullptr, MID, MID);
    mma_gemm<true, false><<<grid_mid, blk, SMEM_TOTAL>>>(
        ah[1], al[1], w_hi + woff[2], w_lo + woff[2], b[2],
        ah[0], al[0], nullptr, MID, MID);
    mma_gemm<true, false><<<grid_mid, blk, SMEM_TOTAL>>>(
        ah[0], al[0], w_hi + woff[3], w_lo + woff[3], b[3],
        ah[1], al[1], nullptr, MID, MID);
    mma_gemm<true, false><<<grid_mid, blk, SMEM_TOTAL>>>(
        ah[1], al[1], w_hi + woff[4], w_lo + woff[4], b[4],
        ah[0], al[0], nullptr, MID, MID);
    // L5: [8192,4096] @ Wt5^T -> [8192,512] fp32, no relu
    mma_gemm<false, true><<<grid_last, blk, SMEM_TOTAL>>>(
        ah[0], al[0], w_hi + woff[5], w_lo + woff[5], b[5],
        nullptr, nullptr, m, HALF, MID);

    int tail = out_size - BATCH * IN_OUT_DIM;
    if (tail < 0) tail = 0;
    finalize_kernel<<<(n_pairs + 255) / 256, 256>>>(x, m, ldj, out, tail);
}

// round 8
// speedup vs baseline: 1.6931x; 1.6931x over previous
#include <cuda_runtime.h>
#include <cuda_fp16.h>
#include <cstdint>

#define BATCH 8192
#define IN_OUT_DIM 1024
#define HALF 512
#define MID 4096

// Weight element offsets in the packed transposed-weight buffers.
#define WO0 0                       // Wt0 [4096,512]
#define WO1 (WO0 + 4096*512)        // Wt1 [4096,4096]
#define WO2 (WO1 + 4096*4096)
#define WO3 (WO2 + 4096*4096)
#define WO4 (WO3 + 4096*4096)
#define WO5 (WO4 + 4096*4096)       // Wt5 [512,4096]
#define WTOT (WO5 + 512*4096)

// ---------------------------------------------------------------------------
// Scratch (allocation-free rule -> device globals)
// ---------------------------------------------------------------------------
__device__ __align__(1024) unsigned short g_odd[BATCH * HALF];        // fp16
__device__ __align__(1024) unsigned short g_a[2][BATCH * MID];        // fp16
__device__ __align__(1024) unsigned short g_w_hi[WTOT];               // fp16
__device__ __align__(1024) unsigned short g_w_lo[WTOT];               // fp16
__device__ __align__(1024) float g_m[BATCH * HALF];

// ---------------------------------------------------------------------------
// PTX helpers (sm_80-level: cp.async, ldmatrix, mma.sync)
// ---------------------------------------------------------------------------
__device__ __forceinline__ uint32_t smem_to_u32(const void* p) {
    uint32_t a;
    asm("{ .reg .u64 t; cvta.to.shared.u64 t, %1; cvt.u32.u64 %0, t; }" : "=r"(a) : "l"(p));
    return a;
}

__device__ __forceinline__ void cp_async16(uint32_t dst, const void* src) {
    asm volatile("cp.async.cg.shared.global [%0], [%1], 16;" :: "r"(dst), "l"(src));
}
__device__ __forceinline__ void cp_commit() {
    asm volatile("cp.async.commit_group;" ::: "memory");
}
template <int N>
__device__ __forceinline__ void cp_wait() {
    asm volatile("cp.async.wait_group %0;" :: "n"(N) : "memory");
}

#define LDMATRIX_X4(r0, r1, r2, r3, addr) \
    asm volatile("ldmatrix.sync.aligned.m8n8.x4.shared.b16 {%0,%1,%2,%3}, [%4];" \
                 : "=r"(r0), "=r"(r1), "=r"(r2), "=r"(r3) : "r"(addr))

// D(f32) += A(f16,row) * B(f16,col);  C/D 4 regs, A 4 regs, B 2 regs
__device__ __forceinline__ void mma_f16(float* c, const uint32_t* a, const uint32_t* b) {
    asm volatile(
        "mma.sync.aligned.m16n8k16.row.col.f32.f16.f16.f32 "
        "{%0,%1,%2,%3}, {%4,%5,%6,%7}, {%8,%9}, {%0,%1,%2,%3};"
        : "+f"(c[0]), "+f"(c[1]), "+f"(c[2]), "+f"(c[3])
        : "r"(a[0]), "r"(a[1]), "r"(a[2]), "r"(a[3]), "r"(b[0]), "r"(b[1]));
}

// ---------------------------------------------------------------------------
// fp32 -> (fp16 hi, fp16 lo) split
// ---------------------------------------------------------------------------
__device__ __forceinline__ void split_f16(float v, unsigned short& h, unsigned short& l) {
    __half hb = __float2half_rn(v);
    float r = v - __half2float(hb);
    __half lb = __float2half_rn(r);
    h = __half_as_ushort(hb);
    l = __half_as_ushort(lb);
}

// ---------------------------------------------------------------------------
// Prep kernels
// ---------------------------------------------------------------------------
__global__ void extract_odd_f16(const float* __restrict__ x,
                                unsigned short* __restrict__ o) {
    int i = blockIdx.x * blockDim.x + threadIdx.x;
    if (i < BATCH * HALF) {
        float2 v = reinterpret_cast<const float2*>(x)[i];
        o[i] = __half_as_ushort(__float2half_rn(v.y));
    }
}

// W [K,N] fp32 (row-major) -> Wt hi/lo [N,K] fp16
__global__ void transpose_split(const float* __restrict__ W,
                                unsigned short* __restrict__ Th,
                                unsigned short* __restrict__ Tl,
                                int K, int N) {
    __shared__ float t[32][33];
    int n0 = blockIdx.x * 32, k0 = blockIdx.y * 32;
    int tx = threadIdx.x, ty = threadIdx.y;
    #pragma unroll
    for (int i = ty; i < 32; i += 8)
        t[i][tx] = W[(size_t)(k0 + i) * N + n0 + tx];
    __syncthreads();
    #pragma unroll
    for (int i = ty; i < 32; i += 8) {
        float v = t[tx][i];
        unsigned short h, l;
        split_f16(v, h, l);
        size_t idx = (size_t)(n0 + i) * K + k0 + tx;
        Th[idx] = h;
        Tl[idx] = l;
    }
}

// ---------------------------------------------------------------------------
// Split-fp16 HMMA GEMM: C[M,N] = A[M,K] @ (Whi+Wlo)[N,K]^T + bias
// A plain fp16; W split hi/lo fp16; fp32 accum.
// BM=128, BN=128, BK=64; 256 threads (8 warps, 2x4 of 64x32 warp tiles);
// 4-stage cp.async pipeline, ONE __syncthreads per mainloop iteration.
// ---------------------------------------------------------------------------
#define BM 128
#define BN 128
#define BK 64
#define NTHREADS 256
#define NSTAGE 4
#define A_OFF 0
#define BH_OFF 16384
#define BL_OFF 32768
#define STAGE_SZ 49152
#define SMEM_TOTAL (NSTAGE * STAGE_SZ + 1024)

// 128B rows (64 fp16): sw = (row*128 + col) ^ ((row&7)<<4)
__device__ __forceinline__ uint32_t swz(int row, int bytecol) {
    return (uint32_t)(row * 128 + bytecol) ^ (uint32_t)((row & 7) << 4);
}

__device__ __forceinline__ void load_stage(
    uint32_t stage_base,
    const unsigned short* A,
    const unsigned short* Bh, const unsigned short* Bl,
    int lda, int tid) {
    // Each operand tile: 128 rows x 128B = 1024 chunks of 16B -> 4 per thread
    #pragma unroll
    for (int j = 0; j < 4; j++) {
        int c = tid + NTHREADS * j;
        int row = c >> 3;
        int col = (c & 7) * 16;
        uint32_t sw = swz(row, col);
        cp_async16(stage_base + A_OFF + sw, (const char*)(A + (size_t)row * lda) + col);
        cp_async16(stage_base + BH_OFF + sw, (const char*)(Bh + (size_t)row * lda) + col);
        cp_async16(stage_base + BL_OFF + sw, (const char*)(Bl + (size_t)row * lda) + col);
    }
}

template <bool RELU, bool FINAL>
__global__ void __launch_bounds__(NTHREADS, 1)
mma_gemm(const unsigned short* __restrict__ A,
         const unsigned short* __restrict__ Bh, const unsigned short* __restrict__ Bl,
         const float* __restrict__ bias,
         unsigned short* __restrict__ C,     // fp16 activation out
         float* __restrict__ Cf,             // fp32 out (FINAL)
         int N, int K) {
    extern __shared__ char dyn_smem[];
    const uint32_t sbase = (smem_to_u32(dyn_smem) + 1023u) & ~1023u;

    const int tid = threadIdx.x;
    const int wid = tid >> 5;
    const int lane = tid & 31;
    const int warp_m = wid & 1;   // 2 warps over M (64 rows each)
    const int warp_n = wid >> 1;  // 4 warps over N (32 cols each)

    const int m0 = blockIdx.y * BM;
    const int n0 = blockIdx.x * BN;
    const unsigned short* At = A + (size_t)m0 * K;
    const unsigned short* Bth = Bh + (size_t)n0 * K;
    const unsigned short* Btl = Bl + (size_t)n0 * K;

    const int niter = K / BK;

    // Prologue: fill NSTAGE-1 stages
    #pragma unroll
    for (int s = 0; s < NSTAGE - 1; s++) {
        load_stage(sbase + s * STAGE_SZ,
                   At + s * BK, Bth + s * BK, Btl + s * BK, K, tid);
        cp_commit();
    }

    float acc[4][4][4];
    #pragma unroll
    for (int mi = 0; mi < 4; mi++)
        #pragma unroll
        for (int nj = 0; nj < 4; nj++)
            #pragma unroll
            for (int q = 0; q < 4; q++) acc[mi][nj][q] = 0.0f;

    // Per-thread ldmatrix address components
    const int a_row_base = warp_m * 64 + (lane & 15);                // + mi*16
    const int a_col_sel = ((lane >> 4) & 1) * 16;                    // + kk*32
    const int b_row_base = warp_n * 32 + (lane & 7) + ((lane >> 4) & 1) * 8;  // + njp*16
    const int b_col_sel = ((lane >> 3) & 1) * 16;                    // + kk*32

    for (int i = 0; i < niter; i++) {
        cp_wait<NSTAGE - 2>();   // stage i resident (2 loads may still fly)
        __syncthreads();         // all warps finished compute(i-1); slot (i-1)%4 free

        if (i + NSTAGE - 1 < niter) {
            int kb = (i + NSTAGE - 1) * BK;
            load_stage(sbase + ((i + NSTAGE - 1) % NSTAGE) * STAGE_SZ,
                       At + kb, Bth + kb, Btl + kb, K, tid);
        }
        cp_commit();  // uniform group accounting (possibly empty)

        const uint32_t so = sbase + (i % NSTAGE) * STAGE_SZ;

        #pragma unroll
        for (int kk = 0; kk < 4; kk++) {
            uint32_t a_r[4][4];
            const int acol = a_col_sel + kk * 32;
            const int bcol = b_col_sel + kk * 32;
            #pragma unroll
            for (int mi = 0; mi < 4; mi++) {
                const int row = a_row_base + mi * 16;
                const uint32_t sw = swz(row, acol);
                LDMATRIX_X4(a_r[mi][0], a_r[mi][1], a_r[mi][2], a_r[mi][3],
                            so + A_OFF + sw);
            }
            #pragma unroll
            for (int njp = 0; njp < 2; njp++) {
                uint32_t b_hi[2][2], b_lo[2][2];
                const int row = b_row_base + njp * 16;
                const uint32_t sw = swz(row, bcol);
                LDMATRIX_X4(b_hi[0][0], b_hi[0][1], b_hi[1][0], b_hi[1][1],
                            so + BH_OFF + sw);
                LDMATRIX_X4(b_lo[0][0], b_lo[0][1], b_lo[1][0], b_lo[1][1],
                            so + BL_OFF + sw);
                #pragma unroll
                for (int mi = 0; mi < 4; mi++) {
                    #pragma unroll
                    for (int njq = 0; njq < 2; njq++) {
                        const int nj = 2 * njp + njq;
                        mma_f16(acc[mi][nj], a_r[mi], b_hi[njq]);
                        mma_f16(acc[mi][nj], a_r[mi], b_lo[njq]);
                    }
                }
            }
        }
    }

    // Epilogue: c0,c1 -> row g, cols p,p+1; c2,c3 -> row g+8
    const int g = lane >> 2;
    const int p = (lane & 3) * 2;
    #pragma unroll
    for (int mi = 0; mi < 4; mi++) {
        #pragma unroll
        for (int nj = 0; nj < 4; nj++) {
            const int col = n0 + warp_n * 32 + nj * 8 + p;
            const float bx = bias[col];
            const float by = bias[col + 1];
            #pragma unroll
            for (int half = 0; half < 2; half++) {
                const int r = m0 + warp_m * 64 + mi * 16 + g + half * 8;
                float v0 = acc[mi][nj][2 * half + 0] + bx;
                float v1 = acc[mi][nj][2 * half + 1] + by;
                if (RELU) {
                    v0 = fmaxf(v0, 0.0f);
                    v1 = fmaxf(v1, 0.0f);
                }
                if (FINAL) {
                    float2 o = make_float2(v0, v1);
                    *reinterpret_cast<float2*>(Cf + (size_t)r * N + col) = o;
                } else {
                    uint32_t h0 = (uint32_t)__half_as_ushort(__float2half_rn(v0));
                    uint32_t h1 = (uint32_t)__half_as_ushort(__float2half_rn(v1));
                    *reinterpret_cast<uint32_t*>(C + (size_t)r * N + col) =
                        (h1 << 16) | h0;
                }
            }
        }
    }
}

// ---------------------------------------------------------------------------
// Finalize: out[b,2k] = x[b,2k] + m[b,k]; out[b,2k+1] = x[b,2k+1]; ldj tail.
// ---------------------------------------------------------------------------
__global__ void finalize_kernel(const float* __restrict__ x,
                                const float* __restrict__ m,
                                const float* __restrict__ ldj,
                                float* __restrict__ out,
                                int tail) {
    int i = blockIdx.x * blockDim.x + threadIdx.x;
    if (i < BATCH * HALF) {
        float2 v = reinterpret_cast<const float2*>(x)[i];
        float2 o;
        o.x = v.x + m[i];
        o.y = v.y;
        reinterpret_cast<float2*>(out)[i] = o;
    }
    if (i < tail) {
        out[BATCH * IN_OUT_DIM + i] = ldj[i];
    }
}

// ---------------------------------------------------------------------------
extern "C" void kernel_launch(void* const* d_in, const int* in_sizes, int n_in,
                              void* d_out, int out_size) {
    const float* x   = (const float*)d_in[0];
    const float* ldj = (const float*)d_in[1];
    const float* W[6] = {(const float*)d_in[2], (const float*)d_in[4],
                         (const float*)d_in[6], (const float*)d_in[8],
                         (const float*)d_in[10], (const float*)d_in[12]};
    const float* b[6] = {(const float*)d_in[3], (const float*)d_in[5],
                         (const float*)d_in[7], (const float*)d_in[9],
                         (const float*)d_in[11], (const float*)d_in[13]};
    float* out = (float*)d_out;

    unsigned short *odd, *a, *w_hi, *w_lo;
    float* m;
    cudaGetSymbolAddress((void**)&odd, g_odd);
    cudaGetSymbolAddress((void**)&a, g_a);
    cudaGetSymbolAddress((void**)&w_hi, g_w_hi);
    cudaGetSymbolAddress((void**)&w_lo, g_w_lo);
    cudaGetSymbolAddress((void**)&m, g_m);

    unsigned short* ab[2] = {a, a + (size_t)BATCH * MID};
    const size_t woff[6] = {WO0, WO1, WO2, WO3, WO4, WO5};

    // --- prep ---
    const int n_pairs = BATCH * HALF;
    extract_odd_f16<<<(n_pairs + 255) / 256, 256>>>(x, odd);

    dim3 tb(32, 8);
    // W0 [512,4096] -> Wt0 [4096,512]
    transpose_split<<<dim3(4096 / 32, 512 / 32), tb>>>(W[0], w_hi + woff[0], w_lo + woff[0], 512, 4096);
    for (int i = 1; i <= 4; i++)
        transpose_split<<<dim3(4096 / 32, 4096 / 32), tb>>>(W[i], w_hi + woff[i], w_lo + woff[i], 4096, 4096);
    // W5 [4096,512] -> Wt5 [512,4096]
    transpose_split<<<dim3(512 / 32, 4096 / 32), tb>>>(W[5], w_hi + woff[5], w_lo + woff[5], 4096, 512);

    // --- GEMM chain ---
    cudaFuncSetAttribute(mma_gemm<true, false>,
                         cudaFuncAttributeMaxDynamicSharedMemorySize, SMEM_TOTAL);
    cudaFuncSetAttribute(mma_gemm<false, true>,
                         cudaFuncAttributeMaxDynamicSharedMemorySize, SMEM_TOTAL);

    dim3 blk(NTHREADS);
    dim3 grid_mid(MID / BN, BATCH / BM);   // (32, 64)
    dim3 grid_last(HALF / BN, BATCH / BM); // (4, 64)

    // L0: [8192,512] @ Wt0^T -> [8192,4096], relu
    mma_gemm<true, false><<<grid_mid, blk, SMEM_TOTAL>>>(
        odd, w_hi + woff[0], w_lo + woff[0], b[0], ab[0], nullptr, MID, HALF);
    // L1..L4: [8192,4096] @ Wt^T -> [8192,4096], relu (ping-pong)
    mma_gemm<true, false><<<grid_mid, blk, SMEM_TOTAL>>>(
        ab[0], w_hi + woff[1], w_lo + woff[1], b[1], ab[1], nullptr, MID, MID);
    mma_gemm<true, false><<<grid_mid, blk, SMEM_TOTAL>>>(
        ab[1], w_hi + woff[2], w_lo + woff[2], b[2], ab[0], nullptr, MID, MID);
    mma_gemm<true, false><<<grid_mid, blk, SMEM_TOTAL>>>(
        ab[0], w_hi + woff[3], w_lo + woff[3], b[3], ab[1], nullptr, MID, MID);
    mma_gemm<true, false><<<grid_mid, blk, SMEM_TOTAL>>>(
        ab[1], w_hi + woff[4], w_lo + woff[4], b[4], ab[0], nullptr, MID, MID);
    // L5: [8192,4096] @ Wt5^T -> [8192,512] fp32, no relu
    mma_gemm<false, true><<<grid_last, blk, SMEM_TOTAL>>>(
        ab[0], w_hi + woff[5], w_lo + woff[5], b[5], nullptr, m, HALF, MID);

    int tail = out_size - BATCH * IN_OUT_DIM;
    if (tail < 0) tail = 0;
    finalize_kernel<<<(n_pairs + 255) / 256, 256>>>(x, m, ldj, out, tail);
}

// round 9
// speedup vs baseline: 2.7302x; 1.6126x over previous
#include <cuda_runtime.h>
#include <cuda_fp16.h>
#include <cstdint>

#define BATCH 8192
#define IN_OUT_DIM 1024
#define HALF 512
#define MID 4096

// Weight element offsets in the packed transposed-weight buffer.
#define WO0 0                       // Wt0 [4096,512]
#define WO1 (WO0 + 4096*512)        // Wt1 [4096,4096]
#define WO2 (WO1 + 4096*4096)
#define WO3 (WO2 + 4096*4096)
#define WO4 (WO3 + 4096*4096)
#define WO5 (WO4 + 4096*4096)       // Wt5 [512,4096]
#define WTOT (WO5 + 512*4096)

// ---------------------------------------------------------------------------
// Scratch (allocation-free rule -> device globals)
// ---------------------------------------------------------------------------
__device__ __align__(1024) unsigned short g_odd[BATCH * HALF];        // fp16
__device__ __align__(1024) unsigned short g_a[2][BATCH * MID];        // fp16
__device__ __align__(1024) unsigned short g_w[WTOT];                  // fp16
__device__ __align__(1024) float g_m[BATCH * HALF];

// ---------------------------------------------------------------------------
// PTX helpers (sm_80-level: cp.async, ldmatrix, mma.sync)
// ---------------------------------------------------------------------------
__device__ __forceinline__ uint32_t smem_to_u32(const void* p) {
    uint32_t a;
    asm("{ .reg .u64 t; cvta.to.shared.u64 t, %1; cvt.u32.u64 %0, t; }" : "=r"(a) : "l"(p));
    return a;
}

__device__ __forceinline__ void cp_async16(uint32_t dst, const void* src) {
    asm volatile("cp.async.cg.shared.global [%0], [%1], 16;" :: "r"(dst), "l"(src));
}
__device__ __forceinline__ void cp_commit() {
    asm volatile("cp.async.commit_group;" ::: "memory");
}
template <int N>
__device__ __forceinline__ void cp_wait() {
    asm volatile("cp.async.wait_group %0;" :: "n"(N) : "memory");
}

#define LDMATRIX_X4(r0, r1, r2, r3, addr) \
    asm volatile("ldmatrix.sync.aligned.m8n8.x4.shared.b16 {%0,%1,%2,%3}, [%4];" \
                 : "=r"(r0), "=r"(r1), "=r"(r2), "=r"(r3) : "r"(addr))

// D(f32) += A(f16,row) * B(f16,col);  C/D 4 regs, A 4 regs, B 2 regs
__device__ __forceinline__ void mma_f16(float* c, const uint32_t* a, const uint32_t* b) {
    asm volatile(
        "mma.sync.aligned.m16n8k16.row.col.f32.f16.f16.f32 "
        "{%0,%1,%2,%3}, {%4,%5,%6,%7}, {%8,%9}, {%0,%1,%2,%3};"
        : "+f"(c[0]), "+f"(c[1]), "+f"(c[2]), "+f"(c[3])
        : "r"(a[0]), "r"(a[1]), "r"(a[2]), "r"(a[3]), "r"(b[0]), "r"(b[1]));
}

// ---------------------------------------------------------------------------
// Prep kernels
// ---------------------------------------------------------------------------
__global__ void extract_odd_f16(const float* __restrict__ x,
                                unsigned short* __restrict__ o) {
    int i = blockIdx.x * blockDim.x + threadIdx.x;
    if (i < BATCH * HALF) {
        float2 v = reinterpret_cast<const float2*>(x)[i];
        o[i] = __half_as_ushort(__float2half_rn(v.y));
    }
}

// W [K,N] fp32 (row-major) -> Wt [N,K] fp16
__global__ void transpose_f16(const float* __restrict__ W,
                              unsigned short* __restrict__ T,
                              int K, int N) {
    __shared__ float t[32][33];
    int n0 = blockIdx.x * 32, k0 = blockIdx.y * 32;
    int tx = threadIdx.x, ty = threadIdx.y;
    #pragma unroll
    for (int i = ty; i < 32; i += 8)
        t[i][tx] = W[(size_t)(k0 + i) * N + n0 + tx];
    __syncthreads();
    #pragma unroll
    for (int i = ty; i < 32; i += 8) {
        float v = t[tx][i];
        T[(size_t)(n0 + i) * K + k0 + tx] = __half_as_ushort(__float2half_rn(v));
    }
}

// ---------------------------------------------------------------------------
// fp16 HMMA GEMM: C[M,N] = A[M,K] @ Wt[N,K]^T + bias, fp32 accum.
// BM=128, BN=128, BK=64; 256 threads (8 warps, 2x4 of 64x32 warp tiles);
// 4-stage cp.async pipeline, ONE __syncthreads per mainloop iteration.
// ---------------------------------------------------------------------------
#define BM 128
#define BN 128
#define BK 64
#define NTHREADS 256
#define NSTAGE 4
#define A_OFF 0
#define B_OFF 16384
#define STAGE_SZ 32768
#define SMEM_TOTAL (NSTAGE * STAGE_SZ + 1024)

// 128B rows (64 fp16): sw = (row*128 + col) ^ ((row&7)<<4)
__device__ __forceinline__ uint32_t swz(int row, int bytecol) {
    return (uint32_t)(row * 128 + bytecol) ^ (uint32_t)((row & 7) << 4);
}

__device__ __forceinline__ void load_stage(
    uint32_t stage_base,
    const unsigned short* A, const unsigned short* B,
    int lda, int tid) {
    // Each operand tile: 128 rows x 128B = 1024 chunks of 16B -> 4 per thread
    #pragma unroll
    for (int j = 0; j < 4; j++) {
        int c = tid + NTHREADS * j;
        int row = c >> 3;
        int col = (c & 7) * 16;
        uint32_t sw = swz(row, col);
        cp_async16(stage_base + A_OFF + sw, (const char*)(A + (size_t)row * lda) + col);
        cp_async16(stage_base + B_OFF + sw, (const char*)(B + (size_t)row * lda) + col);
    }
}

template <bool RELU, bool FINAL>
__global__ void __launch_bounds__(NTHREADS, 1)
mma_gemm(const unsigned short* __restrict__ A,
         const unsigned short* __restrict__ B,
         const float* __restrict__ bias,
         unsigned short* __restrict__ C,     // fp16 activation out
         float* __restrict__ Cf,             // fp32 out (FINAL)
         int N, int K) {
    extern __shared__ char dyn_smem[];
    const uint32_t sbase = (smem_to_u32(dyn_smem) + 1023u) & ~1023u;

    const int tid = threadIdx.x;
    const int wid = tid >> 5;
    const int lane = tid & 31;
    const int warp_m = wid & 1;   // 2 warps over M (64 rows each)
    const int warp_n = wid >> 1;  // 4 warps over N (32 cols each)

    const int m0 = blockIdx.y * BM;
    const int n0 = blockIdx.x * BN;
    const unsigned short* At = A + (size_t)m0 * K;
    const unsigned short* Bt = B + (size_t)n0 * K;

    const int niter = K / BK;

    // Prologue: fill NSTAGE-1 stages
    #pragma unroll
    for (int s = 0; s < NSTAGE - 1; s++) {
        load_stage(sbase + s * STAGE_SZ, At + s * BK, Bt + s * BK, K, tid);
        cp_commit();
    }

    float acc[4][4][4];
    #pragma unroll
    for (int mi = 0; mi < 4; mi++)
        #pragma unroll
        for (int nj = 0; nj < 4; nj++)
            #pragma unroll
            for (int q = 0; q < 4; q++) acc[mi][nj][q] = 0.0f;

    // Per-thread ldmatrix address components
    const int a_row_base = warp_m * 64 + (lane & 15);                // + mi*16
    const int a_col_sel = ((lane >> 4) & 1) * 16;                    // + kk*32
    const int b_row_base = warp_n * 32 + (lane & 7) + ((lane >> 4) & 1) * 8;  // + njp*16
    const int b_col_sel = ((lane >> 3) & 1) * 16;                    // + kk*32

    for (int i = 0; i < niter; i++) {
        cp_wait<NSTAGE - 2>();   // stage i resident
        __syncthreads();         // all warps past compute(i-1); its slot is free

        if (i + NSTAGE - 1 < niter) {
            int kb = (i + NSTAGE - 1) * BK;
            load_stage(sbase + ((i + NSTAGE - 1) % NSTAGE) * STAGE_SZ,
                       At + kb, Bt + kb, K, tid);
        }
        cp_commit();  // uniform group accounting (possibly empty)

        const uint32_t so = sbase + (i % NSTAGE) * STAGE_SZ;

        #pragma unroll
        for (int kk = 0; kk < 4; kk++) {
            uint32_t a_r[4][4];
            const int acol = a_col_sel + kk * 32;
            const int bcol = b_col_sel + kk * 32;
            #pragma unroll
            for (int mi = 0; mi < 4; mi++) {
                const int row = a_row_base + mi * 16;
                const uint32_t sw = swz(row, acol);
                LDMATRIX_X4(a_r[mi][0], a_r[mi][1], a_r[mi][2], a_r[mi][3],
                            so + A_OFF + sw);
            }
            #pragma unroll
            for (int njp = 0; njp < 2; njp++) {
                uint32_t b_r[2][2];
                const int row = b_row_base + njp * 16;
                const uint32_t sw = swz(row, bcol);
                LDMATRIX_X4(b_r[0][0], b_r[0][1], b_r[1][0], b_r[1][1],
                            so + B_OFF + sw);
                #pragma unroll
                for (int mi = 0; mi < 4; mi++) {
                    #pragma unroll
                    for (int njq = 0; njq < 2; njq++) {
                        mma_f16(acc[mi][2 * njp + njq], a_r[mi], b_r[njq]);
                    }
                }
            }
        }
    }

    // Epilogue: c0,c1 -> row g, cols p,p+1; c2,c3 -> row g+8
    const int g = lane >> 2;
    const int p = (lane & 3) * 2;
    #pragma unroll
    for (int mi = 0; mi < 4; mi++) {
        #pragma unroll
        for (int nj = 0; nj < 4; nj++) {
            const int col = n0 + warp_n * 32 + nj * 8 + p;
            const float bx = bias[col];
            const float by = bias[col + 1];
            #pragma unroll
            for (int half = 0; half < 2; half++) {
                const int r = m0 + warp_m * 64 + mi * 16 + g + half * 8;
                float v0 = acc[mi][nj][2 * half + 0] + bx;
                float v1 = acc[mi][nj][2 * half + 1] + by;
                if (RELU) {
                    v0 = fmaxf(v0, 0.0f);
                    v1 = fmaxf(v1, 0.0f);
                }
                if (FINAL) {
                    float2 o = make_float2(v0, v1);
                    *reinterpret_cast<float2*>(Cf + (size_t)r * N + col) = o;
                } else {
                    uint32_t h0 = (uint32_t)__half_as_ushort(__float2half_rn(v0));
                    uint32_t h1 = (uint32_t)__half_as_ushort(__float2half_rn(v1));
                    *reinterpret_cast<uint32_t*>(C + (size_t)r * N + col) =
                        (h1 << 16) | h0;
                }
            }
        }
    }
}

// ---------------------------------------------------------------------------
// Finalize: out[b,2k] = x[b,2k] + m[b,k]; out[b,2k+1] = x[b,2k+1]; ldj tail.
// ---------------------------------------------------------------------------
__global__ void finalize_kernel(const float* __restrict__ x,
                                const float* __restrict__ m,
                                const float* __restrict__ ldj,
                                float* __restrict__ out,
                                int tail) {
    int i = blockIdx.x * blockDim.x + threadIdx.x;
    if (i < BATCH * HALF) {
        float2 v = reinterpret_cast<const float2*>(x)[i];
        float2 o;
        o.x = v.x + m[i];
        o.y = v.y;
        reinterpret_cast<float2*>(out)[i] = o;
    }
    if (i < tail) {
        out[BATCH * IN_OUT_DIM + i] = ldj[i];
    }
}

// ---------------------------------------------------------------------------
extern "C" void kernel_launch(void* const* d_in, const int* in_sizes, int n_in,
                              void* d_out, int out_size) {
    const float* x   = (const float*)d_in[0];
    const float* ldj = (const float*)d_in[1];
    const float* W[6] = {(const float*)d_in[2], (const float*)d_in[4],
                         (const float*)d_in[6], (const float*)d_in[8],
                         (const float*)d_in[10], (const float*)d_in[12]};
    const float* b[6] = {(const float*)d_in[3], (const float*)d_in[5],
                         (const float*)d_in[7], (const float*)d_in[9],
                         (const float*)d_in[11], (const float*)d_in[13]};
    float* out = (float*)d_out;

    unsigned short *odd, *a, *w;
    float* m;
    cudaGetSymbolAddress((void**)&odd, g_odd);
    cudaGetSymbolAddress((void**)&a, g_a);
    cudaGetSymbolAddress((void**)&w, g_w);
    cudaGetSymbolAddress((void**)&m, g_m);

    unsigned short* ab[2] = {a, a + (size_t)BATCH * MID};
    const size_t woff[6] = {WO0, WO1, WO2, WO3, WO4, WO5};

    // --- prep ---
    const int n_pairs = BATCH * HALF;
    extract_odd_f16<<<(n_pairs + 255) / 256, 256>>>(x, odd);

    dim3 tb(32, 8);
    // W0 [512,4096] -> Wt0 [4096,512]
    transpose_f16<<<dim3(4096 / 32, 512 / 32), tb>>>(W[0], w + woff[0], 512, 4096);
    for (int i = 1; i <= 4; i++)
        transpose_f16<<<dim3(4096 / 32, 4096 / 32), tb>>>(W[i], w + woff[i], 4096, 4096);
    // W5 [4096,512] -> Wt5 [512,4096]
    transpose_f16<<<dim3(512 / 32, 4096 / 32), tb>>>(W[5], w + woff[5], 4096, 512);

    // --- GEMM chain ---
    cudaFuncSetAttribute(mma_gemm<true, false>,
                         cudaFuncAttributeMaxDynamicSharedMemorySize, SMEM_TOTAL);
    cudaFuncSetAttribute(mma_gemm<false, true>,
                         cudaFuncAttributeMaxDynamicSharedMemorySize, SMEM_TOTAL);

    dim3 blk(NTHREADS);
    dim3 grid_mid(MID / BN, BATCH / BM);   // (32, 64)
    dim3 grid_last(HALF / BN, BATCH / BM); // (4, 64)

    // L0: [8192,512] @ Wt0^T -> [8192,4096], relu
    mma_gemm<true, false><<<grid_mid, blk, SMEM_TOTAL>>>(
        odd, w + woff[0], b[0], ab[0], nullptr, MID, HALF);
    // L1..L4: [8192,4096] @ Wt^T -> [8192,4096], relu (ping-pong)
    mma_gemm<true, false><<<grid_mid, blk, SMEM_TOTAL>>>(
        ab[0], w + woff[1], b[1], ab[1], nullptr, MID, MID);
    mma_gemm<true, false><<<grid_mid, blk, SMEM_TOTAL>>>(
        ab[1], w + woff[2], b[2], ab[0], nullptr, MID, MID);
    mma_gemm<true, false><<<grid_mid, blk, SMEM_TOTAL>>>(
        ab[0], w + woff[3], b[3], ab[1], nullptr, MID, MID);
    mma_gemm<true, false><<<grid_mid, blk, SMEM_TOTAL>>>(
        ab[1], w + woff[4], b[4], ab[0], nullptr, MID, MID);
    // L5: [8192,4096] @ Wt5^T -> [8192,512] fp32, no relu
    mma_gemm<false, true><<<grid_last, blk, SMEM_TOTAL>>>(
        ab[0], w + woff[5], b[5], nullptr, m, HALF, MID);

    int tail = out_size - BATCH * IN_OUT_DIM;
    if (tail < 0) tail = 0;
    finalize_kernel<<<(n_pairs + 255) / 256, 256>>>(x, m, ldj, out, tail);
}

// round 11
// speedup vs baseline: 3.0742x; 1.1260x over previous
#include <cuda_runtime.h>
#include <cuda_fp16.h>
#include <cstdint>

#define BATCH 8192
#define IN_OUT_DIM 1024
#define HALF 512
#define MID 4096

// Weight element offsets in the packed transposed-weight buffer.
#define WO0 0                       // Wt0 [4096,512]
#define WO1 (WO0 + 4096*512)        // Wt1 [4096,4096]
#define WO2 (WO1 + 4096*4096)
#define WO3 (WO2 + 4096*4096)
#define WO4 (WO3 + 4096*4096)
#define WO5 (WO4 + 4096*4096)       // Wt5 [512,4096]
#define WTOT (WO5 + 512*4096)

// ---------------------------------------------------------------------------
// Scratch (allocation-free rule -> device globals)
// ---------------------------------------------------------------------------
__device__ __align__(1024) unsigned short g_odd[BATCH * HALF];        // fp16
__device__ __align__(1024) unsigned short g_a[2][BATCH * MID];        // fp16
__device__ __align__(1024) unsigned short g_w[WTOT];                  // fp16
__device__ __align__(1024) float g_m[BATCH * HALF];

// ---------------------------------------------------------------------------
// PTX helpers (sm_80-level: cp.async, ldmatrix, mma.sync)
// ---------------------------------------------------------------------------
__device__ __forceinline__ uint32_t smem_to_u32(const void* p) {
    uint32_t a;
    asm("{ .reg .u64 t; cvta.to.shared.u64 t, %1; cvt.u32.u64 %0, t; }" : "=r"(a) : "l"(p));
    return a;
}

__device__ __forceinline__ void cp_async16(uint32_t dst, const void* src) {
    asm volatile("cp.async.cg.shared.global [%0], [%1], 16;" :: "r"(dst), "l"(src));
}
__device__ __forceinline__ void cp_commit() {
    asm volatile("cp.async.commit_group;" ::: "memory");
}
template <int N>
__device__ __forceinline__ void cp_wait() {
    asm volatile("cp.async.wait_group %0;" :: "n"(N) : "memory");
}

#define LDMATRIX_X4(r0, r1, r2, r3, addr) \
    asm volatile("ldmatrix.sync.aligned.m8n8.x4.shared.b16 {%0,%1,%2,%3}, [%4];" \
                 : "=r"(r0), "=r"(r1), "=r"(r2), "=r"(r3) : "r"(addr))

// D(f32) += A(f16,row) * B(f16,col);  C/D 4 regs, A 4 regs, B 2 regs
__device__ __forceinline__ void mma_f16(float* c, const uint32_t* a, const uint32_t* b) {
    asm volatile(
        "mma.sync.aligned.m16n8k16.row.col.f32.f16.f16.f32 "
        "{%0,%1,%2,%3}, {%4,%5,%6,%7}, {%8,%9}, {%0,%1,%2,%3};"
        : "+f"(c[0]), "+f"(c[1]), "+f"(c[2]), "+f"(c[3])
        : "r"(a[0]), "r"(a[1]), "r"(a[2]), "r"(a[3]), "r"(b[0]), "r"(b[1]));
}

// ---------------------------------------------------------------------------
// Prep kernels
// ---------------------------------------------------------------------------
__global__ void extract_odd_f16(const float* __restrict__ x,
                                unsigned short* __restrict__ o) {
    int i = blockIdx.x * blockDim.x + threadIdx.x;
    if (i < BATCH * HALF) {
        float2 v = reinterpret_cast<const float2*>(x)[i];
        o[i] = __half_as_ushort(__float2half_rn(v.y));
    }
}

// W [K,N] fp32 (row-major) -> Wt [N,K] fp16
__global__ void transpose_f16(const float* __restrict__ W,
                              unsigned short* __restrict__ T,
                              int K, int N) {
    __shared__ float t[32][33];
    int n0 = blockIdx.x * 32, k0 = blockIdx.y * 32;
    int tx = threadIdx.x, ty = threadIdx.y;
    #pragma unroll
    for (int i = ty; i < 32; i += 8)
        t[i][tx] = W[(size_t)(k0 + i) * N + n0 + tx];
    __syncthreads();
    #pragma unroll
    for (int i = ty; i < 32; i += 8) {
        float v = t[tx][i];
        T[(size_t)(n0 + i) * K + k0 + tx] = __half_as_ushort(__float2half_rn(v));
    }
}

// ---------------------------------------------------------------------------
// fp16 HMMA GEMM: C[M,N] = A[M,K] @ Wt[N,K]^T + bias, fp32 accum.
// BM=128, BN=128, BK=64; 256 threads (8 warps, 2x4 of 64x32 warp tiles);
// 3-stage cp.async pipeline, ONE __syncthreads per iteration;
// occupancy 2 (two CTAs per SM hide each other's barriers/LDSM latency).
// ---------------------------------------------------------------------------
#define BM 128
#define BN 128
#define BK 64
#define NTHREADS 256
#define NSTAGE 3
#define A_OFF 0
#define B_OFF 16384
#define STAGE_SZ 32768
#define SMEM_TOTAL (NSTAGE * STAGE_SZ + 1024)

// 128B rows (64 fp16): sw = (row*128 + col) ^ ((row&7)<<4)
__device__ __forceinline__ uint32_t swz(int row, int bytecol) {
    return (uint32_t)(row * 128 + bytecol) ^ (uint32_t)((row & 7) << 4);
}

__device__ __forceinline__ void load_stage(
    uint32_t stage_base,
    const unsigned short* A, const unsigned short* B,
    int lda, int tid) {
    // Each operand tile: 128 rows x 128B = 1024 chunks of 16B -> 4 per thread
    #pragma unroll
    for (int j = 0; j < 4; j++) {
        int c = tid + NTHREADS * j;
        int row = c >> 3;
        int col = (c & 7) * 16;
        uint32_t sw = swz(row, col);
        cp_async16(stage_base + A_OFF + sw, (const char*)(A + (size_t)row * lda) + col);
        cp_async16(stage_base + B_OFF + sw, (const char*)(B + (size_t)row * lda) + col);
    }
}

template <bool RELU, bool FINAL>
__global__ void __launch_bounds__(NTHREADS, 2)
mma_gemm(const unsigned short* __restrict__ A,
         const unsigned short* __restrict__ B,
         const float* __restrict__ bias,
         unsigned short* __restrict__ C,     // fp16 activation out
         float* __restrict__ Cf,             // fp32 out (FINAL)
         int N, int K) {
    extern __shared__ char dyn_smem[];
    const uint32_t sbase = (smem_to_u32(dyn_smem) + 1023u) & ~1023u;

    const int tid = threadIdx.x;
    const int wid = tid >> 5;
    const int lane = tid & 31;
    const int warp_m = wid & 1;   // 2 warps over M (64 rows each)
    const int warp_n = wid >> 1;  // 4 warps over N (32 cols each)

    const int m0 = blockIdx.y * BM;
    const int n0 = blockIdx.x * BN;
    const unsigned short* At = A + (size_t)m0 * K;
    const unsigned short* Bt = B + (size_t)n0 * K;

    const int niter = K / BK;

    // Prologue: fill NSTAGE-1 stages
    #pragma unroll
    for (int s = 0; s < NSTAGE - 1; s++) {
        load_stage(sbase + s * STAGE_SZ, At + s * BK, Bt + s * BK, K, tid);
        cp_commit();
    }

    float acc[4][4][4];
    #pragma unroll
    for (int mi = 0; mi < 4; mi++)
        #pragma unroll
        for (int nj = 0; nj < 4; nj++)
            #pragma unroll
            for (int q = 0; q < 4; q++) acc[mi][nj][q] = 0.0f;

    // Per-thread ldmatrix address components
    const int a_row_base = warp_m * 64 + (lane & 15);                // + mi*16
    const int a_col_sel = ((lane >> 4) & 1) * 16;                    // + kk*32
    const int b_row_base = warp_n * 32 + (lane & 7) + ((lane >> 4) & 1) * 8;  // + njp*16
    const int b_col_sel = ((lane >> 3) & 1) * 16;                    // + kk*32

    for (int i = 0; i < niter; i++) {
        cp_wait<NSTAGE - 2>();   // stage i resident
        __syncthreads();         // all warps past compute(i-1); its slot is free

        if (i + NSTAGE - 1 < niter) {
            int kb = (i + NSTAGE - 1) * BK;
            load_stage(sbase + ((i + NSTAGE - 1) % NSTAGE) * STAGE_SZ,
                       At + kb, Bt + kb, K, tid);
        }
        cp_commit();  // uniform group accounting (possibly empty)

        const uint32_t so = sbase + (i % NSTAGE) * STAGE_SZ;

        #pragma unroll
        for (int kk = 0; kk < 4; kk++) {
            uint32_t a_r[4][4];
            const int acol = a_col_sel + kk * 32;
            const int bcol = b_col_sel + kk * 32;
            #pragma unroll
            for (int mi = 0; mi < 4; mi++) {
                const int row = a_row_base + mi * 16;
                const uint32_t sw = swz(row, acol);
                LDMATRIX_X4(a_r[mi][0], a_r[mi][1], a_r[mi][2], a_r[mi][3],
                            so + A_OFF + sw);
            }
            #pragma unroll
            for (int njp = 0; njp < 2; njp++) {
                uint32_t b_r[2][2];
                const int row = b_row_base + njp * 16;
                const uint32_t sw = swz(row, bcol);
                LDMATRIX_X4(b_r[0][0], b_r[0][1], b_r[1][0], b_r[1][1],
                            so + B_OFF + sw);
                #pragma unroll
                for (int mi = 0; mi < 4; mi++) {
                    #pragma unroll
                    for (int njq = 0; njq < 2; njq++) {
                        mma_f16(acc[mi][2 * njp + njq], a_r[mi], b_r[njq]);
                    }
                }
            }
        }
    }

    // Epilogue: c0,c1 -> row g, cols p,p+1; c2,c3 -> row g+8
    const int g = lane >> 2;
    const int p = (lane & 3) * 2;
    #pragma unroll
    for (int mi = 0; mi < 4; mi++) {
        #pragma unroll
        for (int nj = 0; nj < 4; nj++) {
            const int col = n0 + warp_n * 32 + nj * 8 + p;
            const float bx = bias[col];
            const float by = bias[col + 1];
            #pragma unroll
            for (int half = 0; half < 2; half++) {
                const int r = m0 + warp_m * 64 + mi * 16 + g + half * 8;
                float v0 = acc[mi][nj][2 * half + 0] + bx;
                float v1 = acc[mi][nj][2 * half + 1] + by;
                if (RELU) {
                    v0 = fmaxf(v0, 0.0f);
                    v1 = fmaxf(v1, 0.0f);
                }
                if (FINAL) {
                    float2 o = make_float2(v0, v1);
                    *reinterpret_cast<float2*>(Cf + (size_t)r * N + col) = o;
                } else {
                    uint32_t h0 = (uint32_t)__half_as_ushort(__float2half_rn(v0));
                    uint32_t h1 = (uint32_t)__half_as_ushort(__float2half_rn(v1));
                    *reinterpret_cast<uint32_t*>(C + (size_t)r * N + col) =
                        (h1 << 16) | h0;
                }
            }
        }
    }
}

// ---------------------------------------------------------------------------
// Finalize: out[b,2k] = x[b,2k] + m[b,k]; out[b,2k+1] = x[b,2k+1]; ldj tail.
// ---------------------------------------------------------------------------
__global__ void finalize_kernel(const float* __restrict__ x,
                                const float* __restrict__ m,
                                const float* __restrict__ ldj,
                                float* __restrict__ out,
                                int tail) {
    int i = blockIdx.x * blockDim.x + threadIdx.x;
    if (i < BATCH * HALF) {
        float2 v = reinterpret_cast<const float2*>(x)[i];
        float2 o;
        o.x = v.x + m[i];
        o.y = v.y;
        reinterpret_cast<float2*>(out)[i] = o;
    }
    if (i < tail) {
        out[BATCH * IN_OUT_DIM + i] = ldj[i];
    }
}

// ---------------------------------------------------------------------------
extern "C" void kernel_launch(void* const* d_in, const int* in_sizes, int n_in,
                              void* d_out, int out_size) {
    const float* x   = (const float*)d_in[0];
    const float* ldj = (const float*)d_in[1];
    const float* W[6] = {(const float*)d_in[2], (const float*)d_in[4],
                         (const float*)d_in[6], (const float*)d_in[8],
                         (const float*)d_in[10], (const float*)d_in[12]};
    const float* b[6] = {(const float*)d_in[3], (const float*)d_in[5],
                         (const float*)d_in[7], (const float*)d_in[9],
                         (const float*)d_in[11], (const float*)d_in[13]};
    float* out = (float*)d_out;

    unsigned short *odd, *a, *w;
    float* m;
    cudaGetSymbolAddress((void**)&odd, g_odd);
    cudaGetSymbolAddress((void**)&a, g_a);
    cudaGetSymbolAddress((void**)&w, g_w);
    cudaGetSymbolAddress((void**)&m, g_m);

    unsigned short* ab[2] = {a, a + (size_t)BATCH * MID};
    const size_t woff[6] = {WO0, WO1, WO2, WO3, WO4, WO5};

    // --- prep ---
    const int n_pairs = BATCH * HALF;
    extract_odd_f16<<<(n_pairs + 255) / 256, 256>>>(x, odd);

    dim3 tb(32, 8);
    // W0 [512,4096] -> Wt0 [4096,512]
    transpose_f16<<<dim3(4096 / 32, 512 / 32), tb>>>(W[0], w + woff[0], 512, 4096);
    for (int i = 1; i <= 4; i++)
        transpose_f16<<<dim3(4096 / 32, 4096 / 32), tb>>>(W[i], w + woff[i], 4096, 4096);
    // W5 [4096,512] -> Wt5 [512,4096]
    transpose_f16<<<dim3(512 / 32, 4096 / 32), tb>>>(W[5], w + woff[5], 4096, 512);

    // --- GEMM chain ---
    cudaFuncSetAttribute(mma_gemm<true, false>,
                         cudaFuncAttributeMaxDynamicSharedMemorySize, SMEM_TOTAL);
    cudaFuncSetAttribute(mma_gemm<false, true>,
                         cudaFuncAttributeMaxDynamicSharedMemorySize, SMEM_TOTAL);

    dim3 blk(NTHREADS);
    dim3 grid_mid(MID / BN, BATCH / BM);   // (32, 64)
    dim3 grid_last(HALF / BN, BATCH / BM); // (4, 64)

    // L0: [8192,512] @ Wt0^T -> [8192,4096], relu
    mma_gemm<true, false><<<grid_mid, blk, SMEM_TOTAL>>>(
        odd, w + woff[0], b[0], ab[0], nullptr, MID, HALF);
    // L1..L4: [8192,4096] @ Wt^T -> [8192,4096], relu (ping-pong)
    mma_gemm<true, false><<<grid_mid, blk, SMEM_TOTAL>>>(
        ab[0], w + woff[1], b[1], ab[1], nullptr, MID, MID);
    mma_gemm<true, false><<<grid_mid, blk, SMEM_TOTAL>>>(
        ab[1], w + woff[2], b[2], ab[0], nullptr, MID, MID);
    mma_gemm<true, false><<<grid_mid, blk, SMEM_TOTAL>>>(
        ab[0], w + woff[3], b[3], ab[1], nullptr, MID, MID);
    mma_gemm<true, false><<<grid_mid, blk, SMEM_TOTAL>>>(
        ab[1], w + woff[4], b[4], ab[0], nullptr, MID, MID);
    // L5: [8192,4096] @ Wt5^T -> [8192,512] fp32, no relu
    mma_gemm<false, true><<<grid_last, blk, SMEM_TOTAL>>>(
        ab[0], w + woff[5], b[5], nullptr, m, HALF, MID);

    int tail = out_size - BATCH * IN_OUT_DIM;
    if (tail < 0) tail = 0;
    finalize_kernel<<<(n_pairs + 255) / 256, 256>>>(x, m, ldj, out, tail);
}